// round 6
// baseline (speedup 1.0000x reference)
#include <cuda_runtime.h>
#include <math_constants.h>

#define NB 2048
#define VQ_THREADS 256
#define VQ_BLOCKS  (148 * 5)   // one resident wave at 5 blocks/SM

// Shared bucket function — identical ops everywhere (monotone non-decreasing).
__device__ __forceinline__ int bucket_of(float v, float scale, float offs) {
    int b = (int)__fmaf_rn(v, scale, offs);   // FFMA + F2I.TRUNC
    return max(0, min(NB - 1, b));
}

// Predicated shared load: r = (xv > mid) ? *addr : r  (single @p LDS, no branch).
__device__ __forceinline__ void pred_lds_gt(float& r, float xv, float mid, unsigned addr) {
    asm volatile(
        "{ .reg .pred p; setp.gt.f32 p, %1, %2; @p ld.shared.f32 %0, [%3]; }"
        : "+f"(r) : "f"(xv), "f"(mid), "r"(addr));
}

// ---------------------------------------------------------------------------
// Single fused kernel: per-block table build (cheap, deterministic) + stream.
// ---------------------------------------------------------------------------
__global__ __launch_bounds__(VQ_THREADS, 5)
void vq_kernel(const float* __restrict__ w,
               const float4* __restrict__ x4, float4* __restrict__ o4, int n4,
               const float* __restrict__ xt, float* __restrict__ ot, int n_tail) {
    __shared__ float  sw[128];
    __shared__ float  ss[129];      // sorted codes, [128] pad
    __shared__ float  smd[130];     // midpoints, [127..129] = +INF
    __shared__ int    sfb[127];
    __shared__ float2 tabA[NB];     // {vleft, mid}  (mid=+INF if bucket empty)
    __shared__ float  tabB[NB];     // vright (NaN sentinel if >=2 midpoints)
    __shared__ float  s_scale, s_offs;

    const int tid = threadIdx.x;

    // ---- Phase 1: load codebook, rank-sort (128^2, broadcast reads) ----
    if (tid < 128) sw[tid] = w[tid];
    __syncthreads();
    if (tid < 128) {
        const float v = sw[tid];
        int rank = 0;
#pragma unroll 8
        for (int k = 0; k < 128; ++k) {
            const float u = sw[k];
            rank += ((u < v) || (u == v && k < tid)) ? 1 : 0;
        }
        ss[rank] = v;   // unique ranks
    }
    __syncthreads();

    // ---- Phase 2: midpoints + grid transform ----
    if (tid < 127) smd[tid] = 0.5f * (ss[tid] + ss[tid + 1]);
    if (tid >= 127 && tid < 130) smd[tid] = CUDART_INF_F;
    if (tid == 128) ss[128] = 0.0f;
    __syncthreads();
    if (tid == 0) {
        const float lo = smd[0], hi = smd[126];
        const float d = hi - lo;
        float scale, offs;
        if (d > 0.0f && isfinite(d)) {
            scale = (float)NB / d;
            offs  = -lo * scale;
            if (!isfinite(scale) || !isfinite(offs)) { scale = 0.0f; offs = 0.0f; }
        } else { scale = 0.0f; offs = 0.0f; }   // degenerate -> bucket0 -> NaN redo path
        s_scale = scale; s_offs = offs;
    }
    __syncthreads();
    const float scale = s_scale, offs = s_offs;
    if (tid < 127) sfb[tid] = bucket_of(smd[tid], scale, offs);  // non-decreasing
    __syncthreads();

    // ---- Phase 3: build per-bucket {vleft, mid, vright} (8 buckets/thread) ----
#pragma unroll
    for (int q = 0; q < NB / VQ_THREADS; ++q) {
        const int b = tid * (NB / VQ_THREADS) + q;
        int lo = 0, hi = 127;
        while (lo < hi) { int m = (lo + hi) >> 1; if (sfb[m] < b) lo = m + 1; else hi = m; }
        const int base = lo;                        // midpoints strictly before bucket b
        lo = base; hi = 127;
        while (lo < hi) { int m = (lo + hi) >> 1; if (sfb[m] < b + 1) lo = m + 1; else hi = m; }
        const int cnt = lo - base;                  // midpoints inside bucket b

        float2 A; float Bv;
        A.x = ss[base];
        if (cnt == 0)      { A.y = CUDART_INF_F; Bv = A.x; }
        else if (cnt == 1) { A.y = smd[base];    Bv = ss[base + 1]; }
        else               { A.y = smd[base];    Bv = CUDART_NAN_F; }  // redo sentinel
        tabA[b] = A;
        tabB[b] = Bv;
    }
    __syncthreads();

    // ---- Phase 4: software-pipelined stream ----
    const unsigned tabB_base = (unsigned)__cvta_generic_to_shared(tabB);
    const int chunk  = VQ_THREADS * 2;
    const int stride = gridDim.x * chunk;

    float4 cur0, cur1; int h0 = 0, h1 = 0;
    {
        const int ia = blockIdx.x * chunk + tid;
        const int ib = ia + VQ_THREADS;
        h0 = (ia < n4); h1 = (ib < n4);
        if (h0) cur0 = __ldcs(&x4[ia]);
        if (h1) cur1 = __ldcs(&x4[ib]);
    }

    for (int c = blockIdx.x * chunk; c < n4; c += stride) {
        // Prefetch next chunk while current is processed.
        float4 nxt0, nxt1; int g0 = 0, g1 = 0;
        const int cn = c + stride;
        if (cn < n4) {
            const int ia = cn + tid, ib = cn + VQ_THREADS + tid;
            g0 = (ia < n4); g1 = (ib < n4);
            if (g0) nxt0 = __ldcs(&x4[ia]);
            if (g1) nxt1 = __ldcs(&x4[ib]);
        }

#pragma unroll
        for (int k = 0; k < 2; ++k) {
            const int have = k ? h1 : h0;
            if (!have) continue;
            const float4 in = k ? cur1 : cur0;
            float xs[4] = {in.x, in.y, in.z, in.w};
            float rr[4];
#pragma unroll
            for (int e = 0; e < 4; ++e) {
                const float xv = xs[e];
                const int b = bucket_of(xv, scale, offs);
                const float2 a = tabA[b];          // one LDS.64
                float r = a.x;
                pred_lds_gt(r, xv, a.y, tabB_base + (unsigned)b * 4u);
                rr[e] = r;
            }
            // NaN-sentinel detection via FADD propagation (cheap).
            const float acc = (rr[0] + rr[1]) + (rr[2] + rr[3]);
            if (acc != acc) {
                // Rare: exact lower_bound on compact INF-padded tables.
#pragma unroll
                for (int e = 0; e < 4; ++e) {
                    if (rr[e] != rr[e]) {
                        const float xv = xs[e];
                        int j = 0;
#pragma unroll
                        for (int half = 64; half >= 1; half >>= 1)
                            if (smd[j + half - 1] < xv) j += half;
                        rr[e] = ss[j];
                    }
                }
            }
            float4 ov; ov.x = rr[0]; ov.y = rr[1]; ov.z = rr[2]; ov.w = rr[3];
            const int idx = c + k * VQ_THREADS + tid;
            __stcs(&o4[idx], ov);
        }

        cur0 = nxt0; cur1 = nxt1; h0 = g0; h1 = g1;
    }

    // ---- Tail (n % 4), negligible; exact search ----
    if (blockIdx.x == 0 && tid == 0) {
        for (int t = 0; t < n_tail; ++t) {
            const float xv = xt[t];
            int j = 0;
#pragma unroll
            for (int half = 64; half >= 1; half >>= 1)
                if (smd[j + half - 1] < xv) j += half;
            ot[t] = ss[j];
        }
    }
}

extern "C" void kernel_launch(void* const* d_in, const int* in_sizes, int n_in,
                              void* d_out, int out_size) {
    const float* x = (const float*)d_in[0];   // [16,1,512,512] fp32
    const float* w = (const float*)d_in[1];   // [128,1] fp32
    float* out = (float*)d_out;

    const int n = in_sizes[0];
    const int n4 = n >> 2;
    const int n_tail = n & 3;

    vq_kernel<<<VQ_BLOCKS, VQ_THREADS>>>(w, (const float4*)x, (float4*)out, n4,
                                         x + (size_t)n4 * 4, out + (size_t)n4 * 4, n_tail);
}

// round 7
// speedup vs baseline: 1.4199x; 1.4199x over previous
#include <cuda_runtime.h>
#include <math_constants.h>

#define NB 1024
#define VQ_THREADS 256
#define VQ_BLOCKS  (148 * 8)   // one resident wave at 8 blocks/SM

// Globals built by prep each launch (deterministic).
__device__ float2        g_tabA[NB];        // {vleft, mid} per bucket (mid=+INF if no midpoint)
__device__ float         g_tabB[NB];        // vright per bucket (NaN sentinel if >=2 midpoints)
__device__ float         g_sorted[129];     // sorted codes, [128] pad
__device__ float         g_mid[130];        // 127 midpoints, [127..129] = +INF
__device__ float         g_scale, g_offs;

// Shared bucket function — identical ops in prep and main (monotone non-decreasing).
__device__ __forceinline__ int bucket_of(float v, float scale, float offs) {
    int b = (int)__fmaf_rn(v, scale, offs);   // FFMA + F2I.TRUNC
    return max(0, min(NB - 1, b));
}

// ---------------------------------------------------------------------------
// Prep: one block of 1024 threads; trivial cost.
// ---------------------------------------------------------------------------
__global__ void vq_prep(const float* __restrict__ w) {
    __shared__ float sw[128];
    __shared__ float ss[128];
    __shared__ float smd[127];
    __shared__ int   sfb[127];
    __shared__ float s_scale, s_offs;

    const int tid = threadIdx.x;

    if (tid < 128) sw[tid] = w[tid];
    __syncthreads();

    if (tid < 128) {
        float v = sw[tid];
        int rank = 0;
#pragma unroll
        for (int k = 0; k < 128; ++k) {
            float u = sw[k];
            rank += ((u < v) || (u == v && k < tid)) ? 1 : 0;
        }
        ss[rank] = v;   // unique ranks
    }
    __syncthreads();

    if (tid < 128) g_sorted[tid] = ss[tid];
    if (tid == 0)  g_sorted[128] = 0.0f;
    if (tid < 127) {
        float m = 0.5f * (ss[tid] + ss[tid + 1]);
        smd[tid] = m;
        g_mid[tid] = m;
    }
    if (tid >= 127 && tid < 130) g_mid[tid] = CUDART_INF_F;
    __syncthreads();

    if (tid == 0) {
        float lo = smd[0], hi = smd[126];
        float d = hi - lo;
        float scale, offs;
        if (d > 0.0f && isfinite(d)) {
            scale = (float)NB / d;
            offs  = -lo * scale;
            if (!isfinite(scale) || !isfinite(offs)) { scale = 0.0f; offs = 0.0f; }
        } else { scale = 0.0f; offs = 0.0f; }   // degenerate -> bucket0 -> NaN redo path
        s_scale = scale; s_offs = offs;
        g_scale = scale; g_offs = offs;
    }
    __syncthreads();

    const float scale = s_scale, offs = s_offs;
    if (tid < 127) sfb[tid] = bucket_of(smd[tid], scale, offs);  // non-decreasing
    __syncthreads();

    // One thread per bucket (tid < NB).
    if (tid < NB) {
        const int b = tid;
        int lo = 0, hi = 127;
        while (lo < hi) { int m = (lo + hi) >> 1; if (sfb[m] < b) lo = m + 1; else hi = m; }
        const int base = lo;                        // midpoints strictly before bucket b
        lo = base; hi = 127;
        while (lo < hi) { int m = (lo + hi) >> 1; if (sfb[m] < b + 1) lo = m + 1; else hi = m; }
        const int cnt = lo - base;                  // midpoints inside bucket b

        float2 A; float Bv;
        A.x = ss[base];
        if (cnt == 0)      { A.y = CUDART_INF_F; Bv = A.x; }
        else if (cnt == 1) { A.y = smd[base];    Bv = ss[base + 1]; }
        else               { A.y = smd[base];    Bv = CUDART_NAN_F; }  // redo sentinel
        g_tabA[b] = A;
        g_tabB[b] = Bv;
    }
}

// Predicated shared load: r = (xv > mid) ? *addr : r  (single @p LDS, no branch).
__device__ __forceinline__ void pred_lds_gt(float& r, float xv, float mid, unsigned addr) {
    asm volatile(
        "{ .reg .pred p; setp.gt.f32 p, %1, %2; @p ld.shared.f32 %0, [%3]; }"
        : "+f"(r) : "f"(xv), "f"(mid), "r"(addr));
}

// ---------------------------------------------------------------------------
// Main: per element -> bucket (FFMA+F2I+clamp) -> one LDS.64 {vl, mid} ->
// predicated LDS vr. NaN-sentinel redo for >=2-midpoint buckets.
// Full occupancy: 8 blocks/SM, <=32 regs.
// ---------------------------------------------------------------------------
__global__ __launch_bounds__(VQ_THREADS, 8)
void vq_kernel(const float4* __restrict__ x4, float4* __restrict__ o4, int n4,
               const float* __restrict__ xt, float* __restrict__ ot, int n_tail) {
    __shared__ float2 tabA[NB];        // 8 KB
    __shared__ float  tabB[NB];        // 4 KB
    __shared__ float  smid2[130];      // compact, INF-padded (redo path only)
    __shared__ float  scode2[129];

    const int tid = threadIdx.x;

    // Fill tables (coalesced).
#pragma unroll
    for (int i = tid; i < NB; i += VQ_THREADS) {
        tabA[i] = g_tabA[i];
        tabB[i] = g_tabB[i];
    }
    if (tid < 130) smid2[tid] = g_mid[tid];
    if (tid < 129) scode2[tid] = g_sorted[tid];
    const float scale = g_scale;
    const float offs  = g_offs;
    __syncthreads();

    const unsigned tabB_base = (unsigned)__cvta_generic_to_shared(tabB);
    const int chunk = VQ_THREADS * 2;

    for (int c0 = blockIdx.x * chunk; c0 < n4; c0 += gridDim.x * chunk) {
        float4 v[2];
        int have[2];
#pragma unroll
        for (int k = 0; k < 2; ++k) {
            const int idx = c0 + k * VQ_THREADS + tid;
            have[k] = (idx < n4);
            if (have[k]) v[k] = __ldcs(&x4[idx]);
        }

#pragma unroll
        for (int k = 0; k < 2; ++k) {
            if (!have[k]) continue;
            float xs[4] = {v[k].x, v[k].y, v[k].z, v[k].w};
            float rr[4];
#pragma unroll
            for (int e = 0; e < 4; ++e) {
                const float xv = xs[e];
                const int b = bucket_of(xv, scale, offs);
                const float2 a = tabA[b];          // one LDS.64
                float r = a.x;
                pred_lds_gt(r, xv, a.y, tabB_base + (unsigned)b * 4u);
                rr[e] = r;
            }
            // NaN-sentinel detection via FADD propagation (cheap).
            const float acc = (rr[0] + rr[1]) + (rr[2] + rr[3]);
            if (acc != acc) {
                // Rare: exact lower_bound on compact INF-padded tables.
#pragma unroll
                for (int e = 0; e < 4; ++e) {
                    if (rr[e] != rr[e]) {
                        const float xv = xs[e];
                        int j = 0;
#pragma unroll
                        for (int half = 64; half >= 1; half >>= 1)
                            if (smid2[j + half - 1] < xv) j += half;
                        rr[e] = scode2[j];
                    }
                }
            }
            float4 ov; ov.x = rr[0]; ov.y = rr[1]; ov.z = rr[2]; ov.w = rr[3];
            __stcs(&o4[c0 + k * VQ_THREADS + tid], ov);
        }
    }

    // Tail (n % 4), negligible; exact search.
    if (blockIdx.x == 0 && tid == 0) {
        for (int t = 0; t < n_tail; ++t) {
            const float xv = xt[t];
            int j = 0;
#pragma unroll
            for (int half = 64; half >= 1; half >>= 1)
                if (smid2[j + half - 1] < xv) j += half;
            ot[t] = scode2[j];
        }
    }
}

extern "C" void kernel_launch(void* const* d_in, const int* in_sizes, int n_in,
                              void* d_out, int out_size) {
    const float* x = (const float*)d_in[0];   // [16,1,512,512] fp32
    const float* w = (const float*)d_in[1];   // [128,1] fp32
    float* out = (float*)d_out;

    const int n = in_sizes[0];
    const int n4 = n >> 2;
    const int n_tail = n & 3;

    vq_prep<<<1, 1024>>>(w);

    vq_kernel<<<VQ_BLOCKS, VQ_THREADS>>>((const float4*)x, (float4*)out, n4,
                                         x + (size_t)n4 * 4, out + (size_t)n4 * 4, n_tail);
}